// round 9
// baseline (speedup 1.0000x reference)
#include <cuda_runtime.h>

#define B_SZ 65536
#define D_SZ 512
#define V4_PER_ROW (D_SZ / 4)              // 128
#define NC 16
#define NBLOCKS 2048
#define NTHREADS 256
#define WARPS_PER_BLOCK (NTHREADS / 32)    // 8
#define ROWS_PER_WARP 4                    // 2048*8*4 = 65536
#define NPAIR (NC * (NC - 1) / 2)          // 120
#define PAIRS_PER_WARP (NPAIR / WARPS_PER_BLOCK)  // 15

__device__ float g_partials[NBLOCKS];
__device__ unsigned int g_ticket = 0;      // atomicInc wraps to 0 -> graph-replay safe

__global__ __launch_bounds__(NTHREADS, 6) void k_island_fused(
    const float4* __restrict__ x,
    const int* __restrict__ y,             // int32 (JAX x64 disabled)
    const float4* __restrict__ centers,
    float* __restrict__ out)
{
    __shared__ float4 sc[NC * V4_PER_ROW]; // 32 KB center cache (proven R3/R8 config)
    __shared__ float ws[WARPS_PER_BLOCK];
    __shared__ float norms[NC];
    __shared__ float warp_pair[WARPS_PER_BLOCK];
    __shared__ unsigned int s_ticket;

    const int t = threadIdx.x;
    const int lane = t & 31;
    const int wid = t >> 5;

    #pragma unroll
    for (int i = 0; i < (NC * V4_PER_ROW) / NTHREADS; i++)
        sc[i * NTHREADS + t] = centers[i * NTHREADS + t];
    __syncthreads();

    // ---- Phase 1: R8 streaming body, now at 6 CTA/SM ----
    const int gw = blockIdx.x * WARPS_PER_BLOCK + wid;

    float acc = 0.0f;
    #pragma unroll
    for (int r = 0; r < ROWS_PER_WARP; r++) {
        const int row = gw * ROWS_PER_WARP + r;
        const int cls = __ldg(&y[row]) & 15;          // broadcast load
        const float4* __restrict__ xr = x + (size_t)row * V4_PER_ROW;
        const float4* __restrict__ cr = sc + (cls << 7);
        #pragma unroll
        for (int i = 0; i < 4; i++) {
            float4 xv = __ldg(&xr[i * 32 + lane]);    // coalesced 512B
            float4 cv = cr[i * 32 + lane];            // conflict-free LDS.128
            float d0 = xv.x - cv.x;
            float d1 = xv.y - cv.y;
            float d2 = xv.z - cv.z;
            float d3 = xv.w - cv.w;
            acc = fmaf(d0, d0, acc);
            acc = fmaf(d1, d1, acc);
            acc = fmaf(d2, d2, acc);
            acc = fmaf(d3, d3, acc);
        }
    }

    #pragma unroll
    for (int o = 16; o > 0; o >>= 1)
        acc += __shfl_down_sync(0xffffffffu, acc, o);
    if (lane == 0) ws[wid] = acc;
    __syncthreads();
    if (t == 0) {
        float v = 0.f;
        #pragma unroll
        for (int w = 0; w < WARPS_PER_BLOCK; w++) v += ws[w];
        g_partials[blockIdx.x] = v;
        __threadfence();
        s_ticket = atomicInc(&g_ticket, NBLOCKS - 1);
    }
    __syncthreads();
    if (s_ticket != NBLOCKS - 1)
        return;                                       // not the last block

    // ---- Phase 2 (last block only): final reduce + island term ----
    float s = 0.0f;
    #pragma unroll
    for (int i = 0; i < NBLOCKS / NTHREADS; i++)
        s += g_partials[i * NTHREADS + t];
    #pragma unroll
    for (int o = 16; o > 0; o >>= 1)
        s += __shfl_down_sync(0xffffffffu, s, o);
    if (lane == 0) ws[wid] = s;

    // Norms: warp-per-2-rows (centers still resident in sc)
    #pragma unroll
    for (int r = 0; r < 2; r++) {
        const int row = wid * 2 + r;
        const float4* cr = sc + (row << 7);
        float ns = 0.0f;
        #pragma unroll
        for (int i = 0; i < 4; i++) {
            float4 v = cr[i * 32 + lane];
            ns += v.x * v.x + v.y * v.y + v.z * v.z + v.w * v.w;
        }
        #pragma unroll
        for (int o = 16; o > 0; o >>= 1)
            ns += __shfl_down_sync(0xffffffffu, ns, o);
        if (lane == 0) norms[row] = sqrtf(ns);
    }
    __syncthreads();

    // Pairs: 15 per warp, fixed order
    float psum = 0.0f;
    #pragma unroll
    for (int pp = 0; pp < PAIRS_PER_WARP; pp++) {
        const int p = wid * PAIRS_PER_WARP + pp;
        int j = 0, rem = p;
        while (rem >= NC - 1 - j) { rem -= NC - 1 - j; j++; }
        const int k = j + 1 + rem;
        const float4* cj = sc + (j << 7);
        const float4* ck = sc + (k << 7);
        float dot = 0.0f;
        #pragma unroll
        for (int i = 0; i < 4; i++) {
            float4 a = cj[i * 32 + lane];
            float4 b = ck[i * 32 + lane];
            dot += a.x * b.x + a.y * b.y + a.z * b.z + a.w * b.w;
        }
        #pragma unroll
        for (int o = 16; o > 0; o >>= 1)
            dot += __shfl_down_sync(0xffffffffu, dot, o);
        if (lane == 0)
            psum += dot / (norms[j] * norms[k] + 1e-9f) + 1.0f;
    }
    if (lane == 0) warp_pair[wid] = psum;
    __syncthreads();

    if (t == 0) {
        float total = 0.0f;
        float island = 0.0f;
        #pragma unroll
        for (int w = 0; w < WARPS_PER_BLOCK; w++) {
            total += ws[w];
            island += warp_pair[w];
        }
        // SCALE = 1, LAMDA = 1, LAMDA1 = 10
        float loss_center = 0.5f * total * (1.0f / (float)B_SZ);
        out[0] = loss_center + 10.0f * island;
    }
}

extern "C" void kernel_launch(void* const* d_in, const int* in_sizes, int n_in,
                              void* d_out, int out_size)
{
    // Identify inputs by element count (robust to ordering):
    //   output_features: 65536*512 = 33554432
    //   y_truth:         65536
    //   feature_centers: 16*512   = 8192
    const float4* x = nullptr;
    const int* y = nullptr;
    const float4* centers = nullptr;
    for (int i = 0; i < n_in; i++) {
        if (in_sizes[i] == 33554432)      x = (const float4*)d_in[i];
        else if (in_sizes[i] == 65536)    y = (const int*)d_in[i];
        else if (in_sizes[i] == 8192)     centers = (const float4*)d_in[i];
    }
    float* out = (float*)d_out;

    k_island_fused<<<NBLOCKS, NTHREADS>>>(x, y, centers, out);
}

// round 10
// speedup vs baseline: 1.0139x; 1.0139x over previous
#include <cuda_runtime.h>

#define B_SZ 65536
#define D_SZ 512
#define V4_PER_ROW (D_SZ / 4)              // 128
#define TOTAL_V4 (B_SZ * V4_PER_ROW)       // 8,388,608
#define NC 16
#define NBLOCKS 1024
#define NTHREADS 256
#define WARPS_PER_BLOCK (NTHREADS / 32)    // 8
#define GRID_STRIDE (NBLOCKS * NTHREADS)   // 262,144 -> exactly 32 iters/thread
#define OUTER 4                            // 32 iters = 4 outer x MLP 8
#define NPAIR (NC * (NC - 1) / 2)          // 120
#define PAIRS_PER_WARP (NPAIR / WARPS_PER_BLOCK)  // 15

__device__ float g_partials[NBLOCKS];
__device__ unsigned int g_ticket = 0;      // atomicInc wraps to 0 -> graph-replay safe

__global__ __launch_bounds__(NTHREADS) void k_island_fused(
    const float4* __restrict__ x,
    const int* __restrict__ y,             // int32 (JAX x64 disabled)
    const float4* __restrict__ centers,
    float* __restrict__ out)
{
    __shared__ float4 sc[NC * V4_PER_ROW]; // 32 KB center cache (proven)
    __shared__ float ws[WARPS_PER_BLOCK];
    __shared__ float norms[NC];
    __shared__ float warp_pair[WARPS_PER_BLOCK];
    __shared__ unsigned int s_ticket;

    const int t = threadIdx.x;
    const int lane = t & 31;
    const int wid = t >> 5;

    #pragma unroll
    for (int i = 0; i < (NC * V4_PER_ROW) / NTHREADS; i++)
        sc[i * NTHREADS + t] = centers[i * NTHREADS + t];
    __syncthreads();

    // ---- Phase 1: grid-stride, 8 explicit independent LDG.128 per body ----
    float a0 = 0.f, a1 = 0.f, a2 = 0.f, a3 = 0.f;
    int i0 = blockIdx.x * NTHREADS + t;

    #pragma unroll
    for (int outer = 0; outer < OUTER; outer++) {
        const int i1 = i0 + GRID_STRIDE;
        const int i2 = i0 + 2 * GRID_STRIDE;
        const int i3 = i0 + 3 * GRID_STRIDE;
        const int i4 = i0 + 4 * GRID_STRIDE;
        const int i5 = i0 + 5 * GRID_STRIDE;
        const int i6 = i0 + 6 * GRID_STRIDE;
        const int i7 = i0 + 7 * GRID_STRIDE;
        // 8 independent, explicitly named global loads (front-batched)
        float4 x0 = __ldg(&x[i0]);
        float4 x1 = __ldg(&x[i1]);
        float4 x2 = __ldg(&x[i2]);
        float4 x3 = __ldg(&x[i3]);
        float4 x4 = __ldg(&x[i4]);
        float4 x5 = __ldg(&x[i5]);
        float4 x6 = __ldg(&x[i6]);
        float4 x7 = __ldg(&x[i7]);
        float d;
        {
            int c = __ldg(&y[i0 >> 7]) & 15;
            float4 v = sc[(c << 7) + (i0 & 127)];
            d = x0.x - v.x; a0 = fmaf(d, d, a0);
            d = x0.y - v.y; a1 = fmaf(d, d, a1);
            d = x0.z - v.z; a2 = fmaf(d, d, a2);
            d = x0.w - v.w; a3 = fmaf(d, d, a3);
        }
        {
            int c = __ldg(&y[i1 >> 7]) & 15;
            float4 v = sc[(c << 7) + (i1 & 127)];
            d = x1.x - v.x; a0 = fmaf(d, d, a0);
            d = x1.y - v.y; a1 = fmaf(d, d, a1);
            d = x1.z - v.z; a2 = fmaf(d, d, a2);
            d = x1.w - v.w; a3 = fmaf(d, d, a3);
        }
        {
            int c = __ldg(&y[i2 >> 7]) & 15;
            float4 v = sc[(c << 7) + (i2 & 127)];
            d = x2.x - v.x; a0 = fmaf(d, d, a0);
            d = x2.y - v.y; a1 = fmaf(d, d, a1);
            d = x2.z - v.z; a2 = fmaf(d, d, a2);
            d = x2.w - v.w; a3 = fmaf(d, d, a3);
        }
        {
            int c = __ldg(&y[i3 >> 7]) & 15;
            float4 v = sc[(c << 7) + (i3 & 127)];
            d = x3.x - v.x; a0 = fmaf(d, d, a0);
            d = x3.y - v.y; a1 = fmaf(d, d, a1);
            d = x3.z - v.z; a2 = fmaf(d, d, a2);
            d = x3.w - v.w; a3 = fmaf(d, d, a3);
        }
        {
            int c = __ldg(&y[i4 >> 7]) & 15;
            float4 v = sc[(c << 7) + (i4 & 127)];
            d = x4.x - v.x; a0 = fmaf(d, d, a0);
            d = x4.y - v.y; a1 = fmaf(d, d, a1);
            d = x4.z - v.z; a2 = fmaf(d, d, a2);
            d = x4.w - v.w; a3 = fmaf(d, d, a3);
        }
        {
            int c = __ldg(&y[i5 >> 7]) & 15;
            float4 v = sc[(c << 7) + (i5 & 127)];
            d = x5.x - v.x; a0 = fmaf(d, d, a0);
            d = x5.y - v.y; a1 = fmaf(d, d, a1);
            d = x5.z - v.z; a2 = fmaf(d, d, a2);
            d = x5.w - v.w; a3 = fmaf(d, d, a3);
        }
        {
            int c = __ldg(&y[i6 >> 7]) & 15;
            float4 v = sc[(c << 7) + (i6 & 127)];
            d = x6.x - v.x; a0 = fmaf(d, d, a0);
            d = x6.y - v.y; a1 = fmaf(d, d, a1);
            d = x6.z - v.z; a2 = fmaf(d, d, a2);
            d = x6.w - v.w; a3 = fmaf(d, d, a3);
        }
        {
            int c = __ldg(&y[i7 >> 7]) & 15;
            float4 v = sc[(c << 7) + (i7 & 127)];
            d = x7.x - v.x; a0 = fmaf(d, d, a0);
            d = x7.y - v.y; a1 = fmaf(d, d, a1);
            d = x7.z - v.z; a2 = fmaf(d, d, a2);
            d = x7.w - v.w; a3 = fmaf(d, d, a3);
        }
        i0 += 8 * GRID_STRIDE;
    }
    float acc = (a0 + a1) + (a2 + a3);

    #pragma unroll
    for (int o = 16; o > 0; o >>= 1)
        acc += __shfl_down_sync(0xffffffffu, acc, o);
    if (lane == 0) ws[wid] = acc;
    __syncthreads();
    if (t == 0) {
        float v = 0.f;
        #pragma unroll
        for (int w = 0; w < WARPS_PER_BLOCK; w++) v += ws[w];
        g_partials[blockIdx.x] = v;
        __threadfence();
        s_ticket = atomicInc(&g_ticket, NBLOCKS - 1);
    }
    __syncthreads();
    if (s_ticket != NBLOCKS - 1)
        return;                                       // not the last block

    // ---- Phase 2 (last block only): final reduce + island term ----
    float s = 0.0f;
    #pragma unroll
    for (int i = 0; i < NBLOCKS / NTHREADS; i++)
        s += g_partials[i * NTHREADS + t];
    #pragma unroll
    for (int o = 16; o > 0; o >>= 1)
        s += __shfl_down_sync(0xffffffffu, s, o);
    if (lane == 0) ws[wid] = s;

    // Norms: warp-per-2-rows (centers still resident in sc)
    #pragma unroll
    for (int r = 0; r < 2; r++) {
        const int row = wid * 2 + r;
        const float4* cr = sc + (row << 7);
        float ns = 0.0f;
        #pragma unroll
        for (int i = 0; i < 4; i++) {
            float4 v = cr[i * 32 + lane];
            ns += v.x * v.x + v.y * v.y + v.z * v.z + v.w * v.w;
        }
        #pragma unroll
        for (int o = 16; o > 0; o >>= 1)
            ns += __shfl_down_sync(0xffffffffu, ns, o);
        if (lane == 0) norms[row] = sqrtf(ns);
    }
    __syncthreads();

    // Pairs: 15 per warp, fixed order
    float psum = 0.0f;
    #pragma unroll
    for (int pp = 0; pp < PAIRS_PER_WARP; pp++) {
        const int p = wid * PAIRS_PER_WARP + pp;
        int j = 0, rem = p;
        while (rem >= NC - 1 - j) { rem -= NC - 1 - j; j++; }
        const int k = j + 1 + rem;
        const float4* cj = sc + (j << 7);
        const float4* ck = sc + (k << 7);
        float dot = 0.0f;
        #pragma unroll
        for (int i = 0; i < 4; i++) {
            float4 a = cj[i * 32 + lane];
            float4 b = ck[i * 32 + lane];
            dot += a.x * b.x + a.y * b.y + a.z * b.z + a.w * b.w;
        }
        #pragma unroll
        for (int o = 16; o > 0; o >>= 1)
            dot += __shfl_down_sync(0xffffffffu, dot, o);
        if (lane == 0)
            psum += dot / (norms[j] * norms[k] + 1e-9f) + 1.0f;
    }
    if (lane == 0) warp_pair[wid] = psum;
    __syncthreads();

    if (t == 0) {
        float total = 0.0f;
        float island = 0.0f;
        #pragma unroll
        for (int w = 0; w < WARPS_PER_BLOCK; w++) {
            total += ws[w];
            island += warp_pair[w];
        }
        // SCALE = 1, LAMDA = 1, LAMDA1 = 10
        float loss_center = 0.5f * total * (1.0f / (float)B_SZ);
        out[0] = loss_center + 10.0f * island;
    }
}

extern "C" void kernel_launch(void* const* d_in, const int* in_sizes, int n_in,
                              void* d_out, int out_size)
{
    // Identify inputs by element count (robust to ordering):
    //   output_features: 65536*512 = 33554432
    //   y_truth:         65536
    //   feature_centers: 16*512   = 8192
    const float4* x = nullptr;
    const int* y = nullptr;
    const float4* centers = nullptr;
    for (int i = 0; i < n_in; i++) {
        if (in_sizes[i] == 33554432)      x = (const float4*)d_in[i];
        else if (in_sizes[i] == 65536)    y = (const int*)d_in[i];
        else if (in_sizes[i] == 8192)     centers = (const float4*)d_in[i];
    }
    float* out = (float*)d_out;

    k_island_fused<<<NBLOCKS, NTHREADS>>>(x, y, centers, out);
}

// round 11
// speedup vs baseline: 1.1231x; 1.1077x over previous
#include <cuda_runtime.h>

#define B_SZ 65536
#define D_SZ 512
#define V4_PER_ROW (D_SZ / 4)              // 128
#define TOTAL_V4 (B_SZ * V4_PER_ROW)       // 8,388,608
#define NC 16
#define NBLOCKS 2048
#define NTHREADS 256
#define WARPS_PER_BLOCK (NTHREADS / 32)    // 8
#define GRID_STRIDE (NBLOCKS * NTHREADS)   // 524,288 -> exactly 16 iters/thread
#define OUTER 2                            // 16 iters = 2 outer x MLP 8
#define NPAIR (NC * (NC - 1) / 2)          // 120
#define PAIRS_PER_WARP (NPAIR / WARPS_PER_BLOCK)  // 15

// Volatile asm load: ptxas CANNOT reorder these past each other or sink them.
#define LDG128(v, p) \
    asm volatile("ld.global.nc.v4.f32 {%0,%1,%2,%3}, [%4];" \
        : "=f"((v).x), "=f"((v).y), "=f"((v).z), "=f"((v).w) : "l"(p))

__device__ float g_partials[NBLOCKS];
__device__ unsigned int g_ticket = 0;      // atomicInc wraps to 0 -> graph-replay safe

__global__ __launch_bounds__(NTHREADS, 4) void k_island_fused(
    const float4* __restrict__ x,
    const int* __restrict__ y,             // int32 (JAX x64 disabled)
    const float4* __restrict__ centers,
    float* __restrict__ out)
{
    __shared__ float4 sc[NC * V4_PER_ROW]; // 32 KB center cache (proven)
    __shared__ float ws[WARPS_PER_BLOCK];
    __shared__ float norms[NC];
    __shared__ float warp_pair[WARPS_PER_BLOCK];
    __shared__ unsigned int s_ticket;

    const int t = threadIdx.x;
    const int lane = t & 31;
    const int wid = t >> 5;

    #pragma unroll
    for (int i = 0; i < (NC * V4_PER_ROW) / NTHREADS; i++)
        sc[i * NTHREADS + t] = centers[i * NTHREADS + t];
    __syncthreads();

    // ---- Phase 1: 8 FORCED-front-batched LDG.128 per body (asm volatile) ----
    float a0 = 0.f, a1 = 0.f, a2 = 0.f, a3 = 0.f;
    int i0 = blockIdx.x * NTHREADS + t;

    #pragma unroll
    for (int outer = 0; outer < OUTER; outer++) {
        float4 x0, x1, x2, x3, x4, x5, x6, x7;
        LDG128(x0, x + i0);
        LDG128(x1, x + i0 + 1 * GRID_STRIDE);
        LDG128(x2, x + i0 + 2 * GRID_STRIDE);
        LDG128(x3, x + i0 + 3 * GRID_STRIDE);
        LDG128(x4, x + i0 + 4 * GRID_STRIDE);
        LDG128(x5, x + i0 + 5 * GRID_STRIDE);
        LDG128(x6, x + i0 + 6 * GRID_STRIDE);
        LDG128(x7, x + i0 + 7 * GRID_STRIDE);
        float d;
        #pragma unroll
        for (int u = 0; u < 8; u++) {
            const int idx = i0 + u * GRID_STRIDE;
            float4 xv = (u == 0) ? x0 : (u == 1) ? x1 : (u == 2) ? x2 : (u == 3) ? x3
                      : (u == 4) ? x4 : (u == 5) ? x5 : (u == 6) ? x6 : x7;
            const int c = __ldg(&y[idx >> 7]) & 15;
            const float4 v = sc[(c << 7) + (idx & 127)];
            d = xv.x - v.x; a0 = fmaf(d, d, a0);
            d = xv.y - v.y; a1 = fmaf(d, d, a1);
            d = xv.z - v.z; a2 = fmaf(d, d, a2);
            d = xv.w - v.w; a3 = fmaf(d, d, a3);
        }
        i0 += 8 * GRID_STRIDE;
    }
    float acc = (a0 + a1) + (a2 + a3);

    #pragma unroll
    for (int o = 16; o > 0; o >>= 1)
        acc += __shfl_down_sync(0xffffffffu, acc, o);
    if (lane == 0) ws[wid] = acc;
    __syncthreads();
    if (t == 0) {
        float v = 0.f;
        #pragma unroll
        for (int w = 0; w < WARPS_PER_BLOCK; w++) v += ws[w];
        g_partials[blockIdx.x] = v;
        __threadfence();
        s_ticket = atomicInc(&g_ticket, NBLOCKS - 1);
    }
    __syncthreads();
    if (s_ticket != NBLOCKS - 1)
        return;                                       // not the last block

    // ---- Phase 2 (last block only): final reduce + island term ----
    float s = 0.0f;
    #pragma unroll
    for (int i = 0; i < NBLOCKS / NTHREADS; i++)
        s += g_partials[i * NTHREADS + t];
    #pragma unroll
    for (int o = 16; o > 0; o >>= 1)
        s += __shfl_down_sync(0xffffffffu, s, o);
    if (lane == 0) ws[wid] = s;

    // Norms: warp-per-2-rows (centers still resident in sc)
    #pragma unroll
    for (int r = 0; r < 2; r++) {
        const int row = wid * 2 + r;
        const float4* cr = sc + (row << 7);
        float ns = 0.0f;
        #pragma unroll
        for (int i = 0; i < 4; i++) {
            float4 v = cr[i * 32 + lane];
            ns += v.x * v.x + v.y * v.y + v.z * v.z + v.w * v.w;
        }
        #pragma unroll
        for (int o = 16; o > 0; o >>= 1)
            ns += __shfl_down_sync(0xffffffffu, ns, o);
        if (lane == 0) norms[row] = sqrtf(ns);
    }
    __syncthreads();

    // Pairs: 15 per warp, fixed order
    float psum = 0.0f;
    #pragma unroll
    for (int pp = 0; pp < PAIRS_PER_WARP; pp++) {
        const int p = wid * PAIRS_PER_WARP + pp;
        int j = 0, rem = p;
        while (rem >= NC - 1 - j) { rem -= NC - 1 - j; j++; }
        const int k = j + 1 + rem;
        const float4* cj = sc + (j << 7);
        const float4* ck = sc + (k << 7);
        float dot = 0.0f;
        #pragma unroll
        for (int i = 0; i < 4; i++) {
            float4 a = cj[i * 32 + lane];
            float4 b = ck[i * 32 + lane];
            dot += a.x * b.x + a.y * b.y + a.z * b.z + a.w * b.w;
        }
        #pragma unroll
        for (int o = 16; o > 0; o >>= 1)
            dot += __shfl_down_sync(0xffffffffu, dot, o);
        if (lane == 0)
            psum += dot / (norms[j] * norms[k] + 1e-9f) + 1.0f;
    }
    if (lane == 0) warp_pair[wid] = psum;
    __syncthreads();

    if (t == 0) {
        float total = 0.0f;
        float island = 0.0f;
        #pragma unroll
        for (int w = 0; w < WARPS_PER_BLOCK; w++) {
            total += ws[w];
            island += warp_pair[w];
        }
        // SCALE = 1, LAMDA = 1, LAMDA1 = 10
        float loss_center = 0.5f * total * (1.0f / (float)B_SZ);
        out[0] = loss_center + 10.0f * island;
    }
}

extern "C" void kernel_launch(void* const* d_in, const int* in_sizes, int n_in,
                              void* d_out, int out_size)
{
    // Identify inputs by element count (robust to ordering):
    //   output_features: 65536*512 = 33554432
    //   y_truth:         65536
    //   feature_centers: 16*512   = 8192
    const float4* x = nullptr;
    const int* y = nullptr;
    const float4* centers = nullptr;
    for (int i = 0; i < n_in; i++) {
        if (in_sizes[i] == 33554432)      x = (const float4*)d_in[i];
        else if (in_sizes[i] == 65536)    y = (const int*)d_in[i];
        else if (in_sizes[i] == 8192)     centers = (const float4*)d_in[i];
    }
    float* out = (float*)d_out;

    k_island_fused<<<NBLOCKS, NTHREADS>>>(x, y, centers, out);
}